// round 6
// baseline (speedup 1.0000x reference)
#include <cuda_runtime.h>
#include <cuda_bf16.h>
#include <cstdint>

#define KP 6
#define BB 256
#define DD 256
#define NN 50000
#define TOPK 5
#define NTILES 391                        // ceil(NN/128)

// ---------------------------------------------------------------------------
// static device scratch
// ---------------------------------------------------------------------------
__device__ float g_invF[KP * BB];
__device__ float g_invM[KP * NN];
__device__ __nv_bfloat16 g_Asplit[(size_t)KP * BB * 512];   // [k][m][hi|lo]
__device__ __nv_bfloat16 g_Bsplit[(size_t)KP * NN * 512];   // [k][n][hi|lo]
__device__ float g_simScratch[(size_t)KP * BB * NN];        // fallback only
__device__ float2 g_cand[(size_t)KP * BB * NTILES * TOPK];  // (val, idx) per tile

// ---------------------------------------------------------------------------
// helpers
// ---------------------------------------------------------------------------
__device__ __forceinline__ uint32_t smem_u32(const void* p) {
    uint32_t a;
    asm("{ .reg .u64 t; cvta.to.shared.u64 t, %1; cvt.u32.u64 %0, t; }"
        : "=r"(a) : "l"(p));
    return a;
}

#define CP16(dst, src) \
    asm volatile("cp.async.cg.shared.global [%0], [%1], 16;" \
                 :: "r"(dst), "l"(src) : "memory")
#define CP_COMMIT() asm volatile("cp.async.commit_group;" ::: "memory")
#define CP_WAIT3()  asm volatile("cp.async.wait_group 3;" ::: "memory")

#define LDSM4(r, addr)                                                          \
    asm volatile("ldmatrix.sync.aligned.m8n8.x4.shared.b16 {%0,%1,%2,%3}, [%4];"\
                 : "=r"((r)[0]), "=r"((r)[1]), "=r"((r)[2]), "=r"((r)[3])       \
                 : "r"(addr))

#define MMA_BF16(d, a, b)                                                       \
    asm volatile("mma.sync.aligned.m16n8k16.row.col.f32.bf16.bf16.f32 "         \
                 "{%0,%1,%2,%3}, {%4,%5,%6,%7}, {%8,%9}, {%0,%1,%2,%3};"        \
                 : "+f"((d)[0]), "+f"((d)[1]), "+f"((d)[2]), "+f"((d)[3])       \
                 : "r"((a)[0]), "r"((a)[1]), "r"((a)[2]), "r"((a)[3]),          \
                   "r"((b)[0]), "r"((b)[1]))

// ---------------------------------------------------------------------------
// Fused: per-row inverse L2 norm + fp32 -> bf16 hi/lo split. One warp per row.
// ---------------------------------------------------------------------------
__device__ __forceinline__ void split_write4(__nv_bfloat16* drow, int col, float4 v) {
    float xs[4] = {v.x, v.y, v.z, v.w};
    uint32_t hp[2], lp[2];
#pragma unroll
    for (int q = 0; q < 2; ++q) {
        __nv_bfloat16 h0 = __float2bfloat16_rn(xs[2 * q + 0]);
        __nv_bfloat16 h1 = __float2bfloat16_rn(xs[2 * q + 1]);
        __nv_bfloat16 l0 = __float2bfloat16_rn(xs[2 * q + 0] - __bfloat162float(h0));
        __nv_bfloat16 l1 = __float2bfloat16_rn(xs[2 * q + 1] - __bfloat162float(h1));
        hp[q] = (uint32_t)__bfloat16_as_ushort(h0) | ((uint32_t)__bfloat16_as_ushort(h1) << 16);
        lp[q] = (uint32_t)__bfloat16_as_ushort(l0) | ((uint32_t)__bfloat16_as_ushort(l1) << 16);
    }
    *(uint2*)(drow + col)       = make_uint2(hp[0], hp[1]);
    *(uint2*)(drow + 256 + col) = make_uint2(lp[0], lp[1]);
}

__global__ void norm_split_kernel(const float* __restrict__ x,
                                  __nv_bfloat16* __restrict__ dst,
                                  float* __restrict__ inv, int rows) {
    int warp = (blockIdx.x * blockDim.x + threadIdx.x) >> 5;
    int lane = threadIdx.x & 31;
    if (warp >= rows) return;
    const float4* p = (const float4*)(x + (size_t)warp * DD);
    float4 v0 = p[lane];
    float4 v1 = p[lane + 32];
    float s = v0.x * v0.x + v0.y * v0.y + v0.z * v0.z + v0.w * v0.w
            + v1.x * v1.x + v1.y * v1.y + v1.z * v1.z + v1.w * v1.w;
#pragma unroll
    for (int o = 16; o; o >>= 1) s += __shfl_xor_sync(0xFFFFFFFFu, s, o);
    if (lane == 0) inv[warp] = 1.0f / fmaxf(sqrtf(s), 1e-12f);

    __nv_bfloat16* drow = dst + (size_t)warp * 512;
    split_write4(drow, lane * 4, v0);
    split_write4(drow, lane * 4 + 128, v1);
}

// ---------------------------------------------------------------------------
// HMMA GEMM + fused per-tile top-5 candidate extraction.
// Mainloop identical to round-5 (at legacy-HMMA issue ceiling).
// ---------------------------------------------------------------------------
#define BM 128
#define BN 128
#define NCHUNK 24
#define STAGES 5
#define TILE_BYTES (128 * 40 * 2)         // 10240 (80B rows, ldsm conflict-free)
#define STAGE_BYTES (2 * TILE_BYTES)
#define GEMM_SMEM (STAGES * STAGE_BYTES + 1024)
// epilogue fp32 tile (reuses stage smem): 128 rows x 132 floats = 67584 B
#define TROW 132

__global__ void __launch_bounds__(256)
gemm_hmma_kernel(const __nv_bfloat16* __restrict__ Asp,
                 const __nv_bfloat16* __restrict__ Bsp,
                 float* __restrict__ C,
                 const float* __restrict__ invF,
                 const float* __restrict__ invM,
                 float2* __restrict__ cand) {
    extern __shared__ char smem[];
    const int k  = blockIdx.z;
    const int m0 = blockIdx.y * BM;
    const int n0 = blockIdx.x * BN;
    const int tid = threadIdx.x;
    const int wid = tid >> 5, lid = tid & 31;

    float* invFsm = (float*)(smem + STAGES * STAGE_BYTES);
    float* invMsm = invFsm + 128;
    if (tid < 128) {
        invFsm[tid] = invF[k * BB + m0 + tid];
    } else {
        int t = tid - 128;
        int n = n0 + t;
        invMsm[t] = (n < NN) ? invM[k * NN + n] : 0.0f;
    }

    const __nv_bfloat16* Ak = Asp + (size_t)k * BB * 512;
    const __nv_bfloat16* Bk = Bsp + (size_t)k * NN * 512;
    const uint32_t sbase = smem_u32(smem);

    auto issue_chunk = [&](int c) {
        const int t  = c % 3;
        const int kc = c / 3;
        const int aoff = ((t == 1) ? 256 : 0) + kc * 32;
        const int boff = ((t == 2) ? 256 : 0) + kc * 32;
        const uint32_t s = sbase + (c % STAGES) * STAGE_BYTES;
#pragma unroll
        for (int it = 0; it < 2; ++it) {
            int i = tid + it * 256;
            int row = i >> 2, seg = i & 3;
            uint32_t dstA = s + row * 80 + seg * 16;
            const void* srcA = Ak + (size_t)(m0 + row) * 512 + aoff + seg * 8;
            CP16(dstA, srcA);
            int gr = min(n0 + row, NN - 1);
            uint32_t dstB = s + TILE_BYTES + row * 80 + seg * 16;
            const void* srcB = Bk + (size_t)gr * 512 + boff + seg * 8;
            CP16(dstB, srcB);
        }
        CP_COMMIT();
    };

    float acc[4][4][4];
#pragma unroll
    for (int mt = 0; mt < 4; ++mt)
#pragma unroll
        for (int nt = 0; nt < 4; ++nt)
#pragma unroll
            for (int r = 0; r < 4; ++r) acc[mt][nt][r] = 0.0f;

#pragma unroll
    for (int c = 0; c < 4; ++c) issue_chunk(c);

    const int warp_m = wid >> 2;
    const int warp_n = wid & 3;

    for (int c = 0; c < NCHUNK; ++c) {
        CP_WAIT3();
        __syncthreads();
        if (c + 4 < NCHUNK) issue_chunk(c + 4);

        const uint32_t sA = sbase + (c % STAGES) * STAGE_BYTES;
        const uint32_t sB = sA + TILE_BYTES;
#pragma unroll
        for (int ks = 0; ks < 2; ++ks) {
            uint32_t a[4][4], b[4][2];
#pragma unroll
            for (int mt = 0; mt < 4; ++mt) {
                int row = warp_m * 64 + mt * 16 + (lid & 15);
                int col = ks * 16 + (lid >> 4) * 8;
                LDSM4(a[mt], sA + row * 80 + col * 2);
            }
#pragma unroll
            for (int np = 0; np < 2; ++np) {
                uint32_t bb[4];
                int grp = lid >> 3, r = lid & 7;
                int row = warp_n * 32 + np * 16 + (grp >> 1) * 8 + r;
                int col = ks * 16 + (grp & 1) * 8;
                LDSM4(bb, sB + row * 80 + col * 2);
                b[np * 2 + 0][0] = bb[0]; b[np * 2 + 0][1] = bb[1];
                b[np * 2 + 1][0] = bb[2]; b[np * 2 + 1][1] = bb[3];
            }
#pragma unroll
            for (int mt = 0; mt < 4; ++mt)
#pragma unroll
                for (int nt = 0; nt < 4; ++nt)
                    MMA_BF16(acc[mt][nt], a[mt], b[nt]);
        }
    }
    __syncthreads();

    // ---- epilogue: scale, write sim to gmem, stage fp32 tile in smem ----
    float* tile = (float*)smem;   // 128 x TROW, reuses stage smem
    const int g = lid >> 2, tig = lid & 3;
#pragma unroll
    for (int mt = 0; mt < 4; ++mt) {
        int mA = warp_m * 64 + mt * 16;
        float fi0 = invFsm[mA + g];
        float fi1 = invFsm[mA + g + 8];
        float* r0 = C + ((size_t)k * BB + m0 + mA + g) * NN;
        float* r1 = C + ((size_t)k * BB + m0 + mA + g + 8) * NN;
#pragma unroll
        for (int nt = 0; nt < 4; ++nt) {
            int nA = warp_n * 32 + nt * 8 + tig * 2;
            int n = n0 + nA;
            float im0 = invMsm[nA], im1 = invMsm[nA + 1];
            float v00 = acc[mt][nt][0] * fi0 * im0;
            float v01 = acc[mt][nt][1] * fi0 * im1;
            float v10 = acc[mt][nt][2] * fi1 * im0;
            float v11 = acc[mt][nt][3] * fi1 * im1;
            if (n + 1 < NN) {
                *(float2*)(r0 + n) = make_float2(v00, v01);
                *(float2*)(r1 + n) = make_float2(v10, v11);
            } else if (n < NN) {
                r0[n] = v00;
                r1[n] = v10;
            }
            int t0 = (mA + g) * TROW + nA;
            int t1 = (mA + g + 8) * TROW + nA;
            tile[t0]     = (n     < NN) ? v00 : -3.0e38f;
            tile[t0 + 1] = (n + 1 < NN) ? v01 : -3.0e38f;
            tile[t1]     = (n     < NN) ? v10 : -3.0e38f;
            tile[t1 + 1] = (n + 1 < NN) ? v11 : -3.0e38f;
        }
    }
    __syncthreads();

    // ---- per-row top-5 of this 128-col slice -> candidate buffer ----
    // warp w owns rows w*16 .. w*16+15
    for (int rr = 0; rr < 16; ++rr) {
        int r = wid * 16 + rr;
        const float* trow = tile + r * TROW;
        float v0 = trow[lid], v1 = trow[lid + 32],
              v2 = trow[lid + 64], v3 = trow[lid + 96];
        float2* cp = cand +
            ((size_t)(k * BB + m0 + r) * NTILES + blockIdx.x) * TOPK;
#pragma unroll
        for (int round = 0; round < TOPK; ++round) {
            float m = v0; int mc = lid;
            if (v1 > m) { m = v1; mc = lid + 32; }
            if (v2 > m) { m = v2; mc = lid + 64; }
            if (v3 > m) { m = v3; mc = lid + 96; }
#pragma unroll
            for (int off = 16; off; off >>= 1) {
                float om = __shfl_xor_sync(0xFFFFFFFFu, m, off);
                int   oc = __shfl_xor_sync(0xFFFFFFFFu, mc, off);
                if (om > m || (om == m && oc < mc)) { m = om; mc = oc; }
            }
            if (lid == (mc & 31)) {
                int j = mc >> 5;
                if (j == 0) v0 = -3.0e38f;
                else if (j == 1) v1 = -3.0e38f;
                else if (j == 2) v2 = -3.0e38f;
                else v3 = -3.0e38f;
            }
            if (lid == 0) cp[round] = make_float2(m, __int_as_float(n0 + mc));
        }
    }
}

// ---------------------------------------------------------------------------
// Pass 2: per row reduce 391*5 candidates -> global top-5, softmax,
// write the full soft row (zeros + 5 scatter). Replaces memset + old topk.
// ---------------------------------------------------------------------------
__global__ void __launch_bounds__(256)
topk2_kernel(const float2* __restrict__ cand, float* __restrict__ soft) {
    const int row = blockIdx.x;
    const int tid = threadIdx.x;
    const float2* c = cand + (size_t)row * NTILES * TOPK;
    const int NC = NTILES * TOPK;  // 1955

    float tv[TOPK];
    int   ti[TOPK];
#pragma unroll
    for (int i = 0; i < TOPK; ++i) { tv[i] = -3.0e38f; ti[i] = -1; }

    auto insert = [&](float v, int idx) {
        if (v > tv[TOPK - 1]) {
            tv[TOPK - 1] = v; ti[TOPK - 1] = idx;
#pragma unroll
            for (int p = TOPK - 1; p > 0; --p) {
                if (tv[p] > tv[p - 1]) {
                    float t = tv[p]; tv[p] = tv[p - 1]; tv[p - 1] = t;
                    int   q = ti[p]; ti[p] = ti[p - 1]; ti[p - 1] = q;
                }
            }
        }
    };

    for (int i = tid; i < NC; i += 256) {
        float2 p = c[i];
        insert(p.x, __float_as_int(p.y));
    }

    __shared__ float sv[256 * TOPK];
    __shared__ int   si[256 * TOPK];
    __shared__ float rv[256];
    __shared__ int   ri[256];
    __shared__ float winV[TOPK];
    __shared__ int   winI[TOPK];

#pragma unroll
    for (int q = 0; q < TOPK; ++q) {
        sv[tid * TOPK + q] = tv[q];
        si[tid * TOPK + q] = ti[q];
    }
    __syncthreads();

    for (int r = 0; r < TOPK; ++r) {
        float m = -3.0e38f; int ms = -1;
#pragma unroll
        for (int j = 0; j < TOPK; ++j) {
            int slot = tid * TOPK + j;
            if (sv[slot] > m) { m = sv[slot]; ms = slot; }
        }
        rv[tid] = m; ri[tid] = ms;
        __syncthreads();
        for (int off = 128; off; off >>= 1) {
            if (tid < off && rv[tid + off] > rv[tid]) {
                rv[tid] = rv[tid + off]; ri[tid] = ri[tid + off];
            }
            __syncthreads();
        }
        if (tid == 0) {
            int slot = ri[0];
            winV[r] = rv[0];
            winI[r] = si[slot];
            sv[slot] = -3.0e38f;
        }
        __syncthreads();
    }

    // zero the full row (fused memset), then scatter the 5 softmax values
    float* srow = soft + (size_t)row * NN;
    float4 z4 = make_float4(0.f, 0.f, 0.f, 0.f);
    float4* row4 = (float4*)srow;
    for (int i = tid; i < NN / 4; i += 256) row4[i] = z4;
    __syncthreads();

    if (tid == 0) {
        float mx = winV[0];
        float w[TOPK], sum = 0.0f;
#pragma unroll
        for (int q = 0; q < TOPK; ++q) {
            w[q] = __expf((winV[q] - mx) * (1.0f / 3.0f));
            sum += w[q];
        }
        float invSum = 1.0f / sum;
#pragma unroll
        for (int q = 0; q < TOPK; ++q)
            srow[winI[q]] = w[q] * invSum;
    }
}

// ---------------------------------------------------------------------------
extern "C" void kernel_launch(void* const* d_in, const int* in_sizes, int n_in,
                              void* d_out, int out_size) {
    const float* feat = (const float*)d_in[0];  // [KP,BB,DD]
    const float* mem  = (const float*)d_in[1];  // [KP,NN,DD]
    float* out = (float*)d_out;

    const size_t total = (size_t)KP * BB * NN;

    float *invF, *invM;
    __nv_bfloat16 *Asp, *Bsp;
    float2* cand;
    cudaGetSymbolAddress((void**)&invF, g_invF);
    cudaGetSymbolAddress((void**)&invM, g_invM);
    cudaGetSymbolAddress((void**)&Asp, g_Asplit);
    cudaGetSymbolAddress((void**)&Bsp, g_Bsplit);
    cudaGetSymbolAddress((void**)&cand, g_cand);

    float* soft = out;
    float* sim;
    if ((size_t)out_size >= 2 * total) {
        sim = out + total;
    } else {
        cudaGetSymbolAddress((void**)&sim, g_simScratch);
    }

    // fused norm + bf16 hi/lo split
    {
        int rowsF = KP * BB;
        norm_split_kernel<<<(rowsF + 7) / 8, 256>>>(feat, Asp, invF, rowsF);
        int rowsM = KP * NN;
        norm_split_kernel<<<(rowsM + 7) / 8, 256>>>(mem, Bsp, invM, rowsM);
    }

    // HMMA GEMM + per-tile top-5 candidates
    {
        cudaFuncSetAttribute(gemm_hmma_kernel,
                             cudaFuncAttributeMaxDynamicSharedMemorySize, GEMM_SMEM);
        dim3 grid(NTILES, BB / BM, KP);  // (391, 2, 6)
        gemm_hmma_kernel<<<grid, 256, GEMM_SMEM>>>(Asp, Bsp, sim, invF, invM, cand);
    }

    // candidate reduce + softmax + fused zero-write/scatter
    topk2_kernel<<<KP * BB, 256>>>(cand, soft);
}

// round 7
// speedup vs baseline: 1.3061x; 1.3061x over previous
#include <cuda_runtime.h>
#include <cuda_bf16.h>
#include <cstdint>

#define KP 6
#define BB 256
#define DD 256
#define NN 50000
#define TOPK 5

// ---------------------------------------------------------------------------
// static device scratch
// ---------------------------------------------------------------------------
__device__ float g_invF[KP * BB];
__device__ float g_invM[KP * NN];
__device__ __nv_bfloat16 g_Asplit[(size_t)KP * BB * 512];   // [k][m][hi|lo]
__device__ __nv_bfloat16 g_Bsplit[(size_t)KP * NN * 512];   // [k][n][hi|lo]
__device__ float g_simScratch[(size_t)KP * BB * NN];        // fallback only

// ---------------------------------------------------------------------------
// helpers
// ---------------------------------------------------------------------------
__device__ __forceinline__ uint32_t smem_u32(const void* p) {
    uint32_t a;
    asm("{ .reg .u64 t; cvta.to.shared.u64 t, %1; cvt.u32.u64 %0, t; }"
        : "=r"(a) : "l"(p));
    return a;
}

#define CP16(dst, src) \
    asm volatile("cp.async.cg.shared.global [%0], [%1], 16;" \
                 :: "r"(dst), "l"(src) : "memory")
#define CP_COMMIT() asm volatile("cp.async.commit_group;" ::: "memory")
#define CP_WAIT3()  asm volatile("cp.async.wait_group 3;" ::: "memory")

#define LDSM4(r, addr)                                                          \
    asm volatile("ldmatrix.sync.aligned.m8n8.x4.shared.b16 {%0,%1,%2,%3}, [%4];"\
                 : "=r"((r)[0]), "=r"((r)[1]), "=r"((r)[2]), "=r"((r)[3])       \
                 : "r"(addr))

#define MMA_BF16(d, a, b)                                                       \
    asm volatile("mma.sync.aligned.m16n8k16.row.col.f32.bf16.bf16.f32 "         \
                 "{%0,%1,%2,%3}, {%4,%5,%6,%7}, {%8,%9}, {%0,%1,%2,%3};"        \
                 : "+f"((d)[0]), "+f"((d)[1]), "+f"((d)[2]), "+f"((d)[3])       \
                 : "r"((a)[0]), "r"((a)[1]), "r"((a)[2]), "r"((a)[3]),          \
                   "r"((b)[0]), "r"((b)[1]))

// ---------------------------------------------------------------------------
// Fused: per-row inverse L2 norm + fp32 -> bf16 hi/lo split. One warp per row.
// ---------------------------------------------------------------------------
__device__ __forceinline__ void split_write4(__nv_bfloat16* drow, int col, float4 v) {
    float xs[4] = {v.x, v.y, v.z, v.w};
    uint32_t hp[2], lp[2];
#pragma unroll
    for (int q = 0; q < 2; ++q) {
        __nv_bfloat16 h0 = __float2bfloat16_rn(xs[2 * q + 0]);
        __nv_bfloat16 h1 = __float2bfloat16_rn(xs[2 * q + 1]);
        __nv_bfloat16 l0 = __float2bfloat16_rn(xs[2 * q + 0] - __bfloat162float(h0));
        __nv_bfloat16 l1 = __float2bfloat16_rn(xs[2 * q + 1] - __bfloat162float(h1));
        hp[q] = (uint32_t)__bfloat16_as_ushort(h0) | ((uint32_t)__bfloat16_as_ushort(h1) << 16);
        lp[q] = (uint32_t)__bfloat16_as_ushort(l0) | ((uint32_t)__bfloat16_as_ushort(l1) << 16);
    }
    *(uint2*)(drow + col)       = make_uint2(hp[0], hp[1]);
    *(uint2*)(drow + 256 + col) = make_uint2(lp[0], lp[1]);
}

__global__ void norm_split_kernel(const float* __restrict__ x,
                                  __nv_bfloat16* __restrict__ dst,
                                  float* __restrict__ inv, int rows) {
    int warp = (blockIdx.x * blockDim.x + threadIdx.x) >> 5;
    int lane = threadIdx.x & 31;
    if (warp >= rows) return;
    const float4* p = (const float4*)(x + (size_t)warp * DD);
    float4 v0 = p[lane];
    float4 v1 = p[lane + 32];
    float s = v0.x * v0.x + v0.y * v0.y + v0.z * v0.z + v0.w * v0.w
            + v1.x * v1.x + v1.y * v1.y + v1.z * v1.z + v1.w * v1.w;
#pragma unroll
    for (int o = 16; o; o >>= 1) s += __shfl_xor_sync(0xFFFFFFFFu, s, o);
    if (lane == 0) inv[warp] = 1.0f / fmaxf(sqrtf(s), 1e-12f);

    __nv_bfloat16* drow = dst + (size_t)warp * 512;
    split_write4(drow, lane * 4, v0);
    split_write4(drow, lane * 4 + 128, v1);
}

// ---------------------------------------------------------------------------
// HMMA GEMM (round-5 mainloop, at legacy-HMMA issue ceiling) + epilogue that
// also zero-fills the matching soft tile (fused memset, hidden in DRAM slack).
// ---------------------------------------------------------------------------
#define BM 128
#define BN 128
#define NCHUNK 24
#define STAGES 5
#define TILE_BYTES (128 * 40 * 2)         // 10240 (80B rows, ldsm conflict-free)
#define STAGE_BYTES (2 * TILE_BYTES)
#define GEMM_SMEM (STAGES * STAGE_BYTES + 1024)

__global__ void __launch_bounds__(256)
gemm_hmma_kernel(const __nv_bfloat16* __restrict__ Asp,
                 const __nv_bfloat16* __restrict__ Bsp,
                 float* __restrict__ C,
                 float* __restrict__ soft,
                 const float* __restrict__ invF,
                 const float* __restrict__ invM) {
    extern __shared__ char smem[];
    const int k  = blockIdx.z;
    const int m0 = blockIdx.y * BM;
    const int n0 = blockIdx.x * BN;
    const int tid = threadIdx.x;
    const int wid = tid >> 5, lid = tid & 31;

    float* invFsm = (float*)(smem + STAGES * STAGE_BYTES);
    float* invMsm = invFsm + 128;
    if (tid < 128) {
        invFsm[tid] = invF[k * BB + m0 + tid];
    } else {
        int t = tid - 128;
        int n = n0 + t;
        invMsm[t] = (n < NN) ? invM[k * NN + n] : 0.0f;
    }

    const __nv_bfloat16* Ak = Asp + (size_t)k * BB * 512;
    const __nv_bfloat16* Bk = Bsp + (size_t)k * NN * 512;
    const uint32_t sbase = smem_u32(smem);

    // kc-major term order: t0/t1 share the B-hi chunk back-to-back (L2 reuse)
    auto issue_chunk = [&](int c) {
        const int t  = c % 3;
        const int kc = c / 3;
        const int aoff = ((t == 1) ? 256 : 0) + kc * 32;
        const int boff = ((t == 2) ? 256 : 0) + kc * 32;
        const uint32_t s = sbase + (c % STAGES) * STAGE_BYTES;
#pragma unroll
        for (int it = 0; it < 2; ++it) {
            int i = tid + it * 256;
            int row = i >> 2, seg = i & 3;
            uint32_t dstA = s + row * 80 + seg * 16;
            const void* srcA = Ak + (size_t)(m0 + row) * 512 + aoff + seg * 8;
            CP16(dstA, srcA);
            int gr = min(n0 + row, NN - 1);
            uint32_t dstB = s + TILE_BYTES + row * 80 + seg * 16;
            const void* srcB = Bk + (size_t)gr * 512 + boff + seg * 8;
            CP16(dstB, srcB);
        }
        CP_COMMIT();
    };

    float acc[4][4][4];
#pragma unroll
    for (int mt = 0; mt < 4; ++mt)
#pragma unroll
        for (int nt = 0; nt < 4; ++nt)
#pragma unroll
            for (int r = 0; r < 4; ++r) acc[mt][nt][r] = 0.0f;

#pragma unroll
    for (int c = 0; c < 4; ++c) issue_chunk(c);

    const int warp_m = wid >> 2;     // 0..1 (64 rows)
    const int warp_n = wid & 3;      // 0..3 (32 cols)

    for (int c = 0; c < NCHUNK; ++c) {
        CP_WAIT3();
        __syncthreads();
        if (c + 4 < NCHUNK) issue_chunk(c + 4);

        const uint32_t sA = sbase + (c % STAGES) * STAGE_BYTES;
        const uint32_t sB = sA + TILE_BYTES;
#pragma unroll
        for (int ks = 0; ks < 2; ++ks) {
            uint32_t a[4][4], b[4][2];
#pragma unroll
            for (int mt = 0; mt < 4; ++mt) {
                int row = warp_m * 64 + mt * 16 + (lid & 15);
                int col = ks * 16 + (lid >> 4) * 8;
                LDSM4(a[mt], sA + row * 80 + col * 2);
            }
#pragma unroll
            for (int np = 0; np < 2; ++np) {
                uint32_t bb[4];
                int grp = lid >> 3, r = lid & 7;
                int row = warp_n * 32 + np * 16 + (grp >> 1) * 8 + r;
                int col = ks * 16 + (grp & 1) * 8;
                LDSM4(bb, sB + row * 80 + col * 2);
                b[np * 2 + 0][0] = bb[0]; b[np * 2 + 0][1] = bb[1];
                b[np * 2 + 1][0] = bb[2]; b[np * 2 + 1][1] = bb[3];
            }
#pragma unroll
            for (int mt = 0; mt < 4; ++mt)
#pragma unroll
                for (int nt = 0; nt < 4; ++nt)
                    MMA_BF16(acc[mt][nt], a[mt], b[nt]);
        }
    }
    __syncthreads();

    // epilogue: write sim + zero-fill the matching soft tile (fused memset)
    const int g = lid >> 2, tig = lid & 3;
    const float2 z2 = make_float2(0.f, 0.f);
#pragma unroll
    for (int mt = 0; mt < 4; ++mt) {
        int mA = warp_m * 64 + mt * 16;
        float fi0 = invFsm[mA + g];
        float fi1 = invFsm[mA + g + 8];
        size_t row0 = (size_t)k * BB + m0 + mA + g;
        float* r0 = C + row0 * NN;
        float* r1 = r0 + 8 * NN;
        float* z0 = soft + row0 * NN;
        float* z1 = z0 + 8 * NN;
#pragma unroll
        for (int nt = 0; nt < 4; ++nt) {
            int nA = warp_n * 32 + nt * 8 + tig * 2;
            int n = n0 + nA;
            if (n + 1 < NN) {
                float im0 = invMsm[nA], im1 = invMsm[nA + 1];
                *(float2*)(r0 + n) = make_float2(acc[mt][nt][0] * fi0 * im0,
                                                 acc[mt][nt][1] * fi0 * im1);
                *(float2*)(r1 + n) = make_float2(acc[mt][nt][2] * fi1 * im0,
                                                 acc[mt][nt][3] * fi1 * im1);
                *(float2*)(z0 + n) = z2;
                *(float2*)(z1 + n) = z2;
            } else if (n < NN) {
                float im0 = invMsm[nA];
                r0[n] = acc[mt][nt][0] * fi0 * im0;
                r1[n] = acc[mt][nt][2] * fi1 * im0;
                z0[n] = 0.f;
                z1[n] = 0.f;
            }
        }
    }
}

// ---------------------------------------------------------------------------
// Per (k,b) row: top-5 of 50000 (ILP-4, single 16-wide gate), softmax,
// scatter 5 values into the pre-zeroed soft row.
// ---------------------------------------------------------------------------
__global__ void __launch_bounds__(256)
topk_kernel(const float* __restrict__ sim, float* __restrict__ soft) {
    const int row = blockIdx.x;
    const float* s = sim + (size_t)row * NN;
    const int tid = threadIdx.x;

    float tv[TOPK];
    int   ti[TOPK];
#pragma unroll
    for (int i = 0; i < TOPK; ++i) { tv[i] = -3.0e38f; ti[i] = -1; }

    auto insert = [&](float v, int idx) {
        if (v > tv[TOPK - 1]) {
            tv[TOPK - 1] = v; ti[TOPK - 1] = idx;
#pragma unroll
            for (int p = TOPK - 1; p > 0; --p) {
                if (tv[p] > tv[p - 1]) {
                    float t = tv[p]; tv[p] = tv[p - 1]; tv[p - 1] = t;
                    int   q = ti[p]; ti[p] = ti[p - 1]; ti[p - 1] = q;
                }
            }
        }
    };
    auto scan4 = [&](float4 v, int b) {
        insert(v.x, b + 0);
        insert(v.y, b + 1);
        insert(v.z, b + 2);
        insert(v.w, b + 3);
    };

    const float4* s4 = (const float4*)s;
    const int NV = NN / 4;  // 12500
    int i = tid;
    for (; i + 768 < NV; i += 1024) {
        float4 v0 = s4[i];
        float4 v1 = s4[i + 256];
        float4 v2 = s4[i + 512];
        float4 v3 = s4[i + 768];
        float m01 = fmaxf(fmaxf(v0.x, v0.y), fmaxf(v0.z, v0.w));
        float m23 = fmaxf(fmaxf(v1.x, v1.y), fmaxf(v1.z, v1.w));
        float m45 = fmaxf(fmaxf(v2.x, v2.y), fmaxf(v2.z, v2.w));
        float m67 = fmaxf(fmaxf(v3.x, v3.y), fmaxf(v3.z, v3.w));
        float mall = fmaxf(fmaxf(m01, m23), fmaxf(m45, m67));
        if (mall > tv[TOPK - 1]) {
            if (m01 > tv[TOPK - 1]) scan4(v0, 4 * i);
            if (m23 > tv[TOPK - 1]) scan4(v1, 4 * (i + 256));
            if (m45 > tv[TOPK - 1]) scan4(v2, 4 * (i + 512));
            if (m67 > tv[TOPK - 1]) scan4(v3, 4 * (i + 768));
        }
    }
    for (; i < NV; i += 256) {
        float4 v = s4[i];
        float m4 = fmaxf(fmaxf(v.x, v.y), fmaxf(v.z, v.w));
        if (m4 > tv[TOPK - 1]) scan4(v, 4 * i);
    }

    __shared__ float sv[256 * TOPK];
    __shared__ int   si[256 * TOPK];
    __shared__ float rv[256];
    __shared__ int   ri[256];
    __shared__ float winV[TOPK];
    __shared__ int   winI[TOPK];

#pragma unroll
    for (int q = 0; q < TOPK; ++q) {
        sv[tid * TOPK + q] = tv[q];
        si[tid * TOPK + q] = ti[q];
    }
    __syncthreads();

    for (int r = 0; r < TOPK; ++r) {
        float m = -3.0e38f; int ms = -1;
#pragma unroll
        for (int j = 0; j < TOPK; ++j) {
            int slot = tid * TOPK + j;
            if (sv[slot] > m) { m = sv[slot]; ms = slot; }
        }
        rv[tid] = m; ri[tid] = ms;
        __syncthreads();
        for (int off = 128; off; off >>= 1) {
            if (tid < off && rv[tid + off] > rv[tid]) {
                rv[tid] = rv[tid + off]; ri[tid] = ri[tid + off];
            }
            __syncthreads();
        }
        if (tid == 0) {
            int slot = ri[0];
            winV[r] = rv[0];
            winI[r] = si[slot];
            sv[slot] = -3.0e38f;
        }
        __syncthreads();
    }

    if (tid == 0) {
        float mx = winV[0];
        float w[TOPK], sum = 0.0f;
#pragma unroll
        for (int q = 0; q < TOPK; ++q) {
            w[q] = __expf((winV[q] - mx) * (1.0f / 3.0f));
            sum += w[q];
        }
        float invSum = 1.0f / sum;
        float* srow = soft + (size_t)row * NN;
#pragma unroll
        for (int q = 0; q < TOPK; ++q)
            srow[winI[q]] = w[q] * invSum;
    }
}

// ---------------------------------------------------------------------------
extern "C" void kernel_launch(void* const* d_in, const int* in_sizes, int n_in,
                              void* d_out, int out_size) {
    const float* feat = (const float*)d_in[0];  // [KP,BB,DD]
    const float* mem  = (const float*)d_in[1];  // [KP,NN,DD]
    float* out = (float*)d_out;

    const size_t total = (size_t)KP * BB * NN;

    float *invF, *invM;
    __nv_bfloat16 *Asp, *Bsp;
    cudaGetSymbolAddress((void**)&invF, g_invF);
    cudaGetSymbolAddress((void**)&invM, g_invM);
    cudaGetSymbolAddress((void**)&Asp, g_Asplit);
    cudaGetSymbolAddress((void**)&Bsp, g_Bsplit);

    float* soft = out;
    float* sim;
    if ((size_t)out_size >= 2 * total) {
        sim = out + total;
    } else {
        cudaGetSymbolAddress((void**)&sim, g_simScratch);
    }

    // fused norm + bf16 hi/lo split
    {
        int rowsF = KP * BB;
        norm_split_kernel<<<(rowsF + 7) / 8, 256>>>(feat, Asp, invF, rowsF);
        int rowsM = KP * NN;
        norm_split_kernel<<<(rowsM + 7) / 8, 256>>>(mem, Bsp, invM, rowsM);
    }

    // HMMA GEMM (+ fused zero-fill of soft)
    {
        cudaFuncSetAttribute(gemm_hmma_kernel,
                             cudaFuncAttributeMaxDynamicSharedMemorySize, GEMM_SMEM);
        dim3 grid((NN + BN - 1) / BN, BB / BM, KP);  // (391, 2, 6)
        gemm_hmma_kernel<<<grid, 256, GEMM_SMEM>>>(Asp, Bsp, sim, soft, invF, invM);
    }

    // top-5 + softmax scatter (soft rows already zeroed)
    topk_kernel<<<KP * BB, 256>>>(sim, soft);
}

// round 9
// speedup vs baseline: 1.4616x; 1.1191x over previous
#include <cuda_runtime.h>
#include <cuda_bf16.h>
#include <cstdint>

#define KP 6
#define BB 256
#define DD 256
#define NN 50000
#define TOPK 5
#define NTILES 391                         // ceil(NN/128)

// ---------------------------------------------------------------------------
// static device scratch
// ---------------------------------------------------------------------------
__device__ float g_invF[KP * BB];
__device__ float g_invM[KP * NN];
__device__ __nv_bfloat16 g_Asplit[(size_t)KP * BB * 512];   // [k][m][hi|lo]
__device__ __nv_bfloat16 g_Bsplit[(size_t)KP * NN * 512];   // [k][n][hi|lo]
__device__ float g_simScratch[(size_t)KP * BB * NN];        // fallback only
__device__ float g_bmax[(size_t)KP * BB * NTILES];          // per-row per-tile max

// ---------------------------------------------------------------------------
// helpers
// ---------------------------------------------------------------------------
__device__ __forceinline__ uint32_t smem_u32(const void* p) {
    uint32_t a;
    asm("{ .reg .u64 t; cvta.to.shared.u64 t, %1; cvt.u32.u64 %0, t; }"
        : "=r"(a) : "l"(p));
    return a;
}

#define CP16(dst, src) \
    asm volatile("cp.async.cg.shared.global [%0], [%1], 16;" \
                 :: "r"(dst), "l"(src) : "memory")
#define CP_COMMIT() asm volatile("cp.async.commit_group;" ::: "memory")
#define CP_WAIT3()  asm volatile("cp.async.wait_group 3;" ::: "memory")

#define LDSM4(r, addr)                                                          \
    asm volatile("ldmatrix.sync.aligned.m8n8.x4.shared.b16 {%0,%1,%2,%3}, [%4];"\
                 : "=r"((r)[0]), "=r"((r)[1]), "=r"((r)[2]), "=r"((r)[3])       \
                 : "r"(addr))

#define MMA_BF16(d, a, b)                                                       \
    asm volatile("mma.sync.aligned.m16n8k16.row.col.f32.bf16.bf16.f32 "         \
                 "{%0,%1,%2,%3}, {%4,%5,%6,%7}, {%8,%9}, {%0,%1,%2,%3};"        \
                 : "+f"((d)[0]), "+f"((d)[1]), "+f"((d)[2]), "+f"((d)[3])       \
                 : "r"((a)[0]), "r"((a)[1]), "r"((a)[2]), "r"((a)[3]),          \
                   "r"((b)[0]), "r"((b)[1]))

// ---------------------------------------------------------------------------
// Fused: per-row inverse L2 norm + fp32 -> bf16 hi/lo split. One warp per row.
// ---------------------------------------------------------------------------
__device__ __forceinline__ void split_write4(__nv_bfloat16* drow, int col, float4 v) {
    float xs[4] = {v.x, v.y, v.z, v.w};
    uint32_t hp[2], lp[2];
#pragma unroll
    for (int q = 0; q < 2; ++q) {
        __nv_bfloat16 h0 = __float2bfloat16_rn(xs[2 * q + 0]);
        __nv_bfloat16 h1 = __float2bfloat16_rn(xs[2 * q + 1]);
        __nv_bfloat16 l0 = __float2bfloat16_rn(xs[2 * q + 0] - __bfloat162float(h0));
        __nv_bfloat16 l1 = __float2bfloat16_rn(xs[2 * q + 1] - __bfloat162float(h1));
        hp[q] = (uint32_t)__bfloat16_as_ushort(h0) | ((uint32_t)__bfloat16_as_ushort(h1) << 16);
        lp[q] = (uint32_t)__bfloat16_as_ushort(l0) | ((uint32_t)__bfloat16_as_ushort(l1) << 16);
    }
    *(uint2*)(drow + col)       = make_uint2(hp[0], hp[1]);
    *(uint2*)(drow + 256 + col) = make_uint2(lp[0], lp[1]);
}

__global__ void norm_split_kernel(const float* __restrict__ x,
                                  __nv_bfloat16* __restrict__ dst,
                                  float* __restrict__ inv, int rows) {
    int warp = (blockIdx.x * blockDim.x + threadIdx.x) >> 5;
    int lane = threadIdx.x & 31;
    if (warp >= rows) return;
    const float4* p = (const float4*)(x + (size_t)warp * DD);
    float4 v0 = p[lane];
    float4 v1 = p[lane + 32];
    float s = v0.x * v0.x + v0.y * v0.y + v0.z * v0.z + v0.w * v0.w
            + v1.x * v1.x + v1.y * v1.y + v1.z * v1.z + v1.w * v1.w;
#pragma unroll
    for (int o = 16; o; o >>= 1) s += __shfl_xor_sync(0xFFFFFFFFu, s, o);
    if (lane == 0) inv[warp] = 1.0f / fmaxf(sqrtf(s), 1e-12f);

    __nv_bfloat16* drow = dst + (size_t)warp * 512;
    split_write4(drow, lane * 4, v0);
    split_write4(drow, lane * 4 + 128, v1);
}

// ---------------------------------------------------------------------------
// HMMA GEMM + fused soft zero-fill + per-(row,tile) max into g_bmax.
// ---------------------------------------------------------------------------
#define BM 128
#define BN 128
#define NCHUNK 24
#define STAGES 5
#define TILE_BYTES (128 * 40 * 2)         // 10240 (80B rows, ldsm conflict-free)
#define STAGE_BYTES (2 * TILE_BYTES)
#define GEMM_SMEM (STAGES * STAGE_BYTES + 1024)

__global__ void __launch_bounds__(256)
gemm_hmma_kernel(const __nv_bfloat16* __restrict__ Asp,
                 const __nv_bfloat16* __restrict__ Bsp,
                 float* __restrict__ C,
                 float* __restrict__ soft,
                 const float* __restrict__ invF,
                 const float* __restrict__ invM,
                 float* __restrict__ bmax) {
    extern __shared__ char smem[];
    const int k  = blockIdx.z;
    const int m0 = blockIdx.y * BM;
    const int n0 = blockIdx.x * BN;
    const int tid = threadIdx.x;
    const int wid = tid >> 5, lid = tid & 31;

    float* invFsm = (float*)(smem + STAGES * STAGE_BYTES);
    float* invMsm = invFsm + 128;
    if (tid < 128) {
        invFsm[tid] = invF[k * BB + m0 + tid];
    } else {
        int t = tid - 128;
        int n = n0 + t;
        invMsm[t] = (n < NN) ? invM[k * NN + n] : 0.0f;
    }

    const __nv_bfloat16* Ak = Asp + (size_t)k * BB * 512;
    const __nv_bfloat16* Bk = Bsp + (size_t)k * NN * 512;
    const uint32_t sbase = smem_u32(smem);

    auto issue_chunk = [&](int c) {
        const int t  = c % 3;
        const int kc = c / 3;
        const int aoff = ((t == 1) ? 256 : 0) + kc * 32;
        const int boff = ((t == 2) ? 256 : 0) + kc * 32;
        const uint32_t s = sbase + (c % STAGES) * STAGE_BYTES;
#pragma unroll
        for (int it = 0; it < 2; ++it) {
            int i = tid + it * 256;
            int row = i >> 2, seg = i & 3;
            uint32_t dstA = s + row * 80 + seg * 16;
            const void* srcA = Ak + (size_t)(m0 + row) * 512 + aoff + seg * 8;
            CP16(dstA, srcA);
            int gr = min(n0 + row, NN - 1);
            uint32_t dstB = s + TILE_BYTES + row * 80 + seg * 16;
            const void* srcB = Bk + (size_t)gr * 512 + boff + seg * 8;
            CP16(dstB, srcB);
        }
        CP_COMMIT();
    };

    float acc[4][4][4];
#pragma unroll
    for (int mt = 0; mt < 4; ++mt)
#pragma unroll
        for (int nt = 0; nt < 4; ++nt)
#pragma unroll
            for (int r = 0; r < 4; ++r) acc[mt][nt][r] = 0.0f;

#pragma unroll
    for (int c = 0; c < 4; ++c) issue_chunk(c);

    const int warp_m = wid >> 2;
    const int warp_n = wid & 3;

    for (int c = 0; c < NCHUNK; ++c) {
        CP_WAIT3();
        __syncthreads();
        if (c + 4 < NCHUNK) issue_chunk(c + 4);

        const uint32_t sA = sbase + (c % STAGES) * STAGE_BYTES;
        const uint32_t sB = sA + TILE_BYTES;
#pragma unroll
        for (int ks = 0; ks < 2; ++ks) {
            uint32_t a[4][4], b[4][2];
#pragma unroll
            for (int mt = 0; mt < 4; ++mt) {
                int row = warp_m * 64 + mt * 16 + (lid & 15);
                int col = ks * 16 + (lid >> 4) * 8;
                LDSM4(a[mt], sA + row * 80 + col * 2);
            }
#pragma unroll
            for (int np = 0; np < 2; ++np) {
                uint32_t bb[4];
                int grp = lid >> 3, r = lid & 7;
                int row = warp_n * 32 + np * 16 + (grp >> 1) * 8 + r;
                int col = ks * 16 + (grp & 1) * 8;
                LDSM4(bb, sB + row * 80 + col * 2);
                b[np * 2 + 0][0] = bb[0]; b[np * 2 + 0][1] = bb[1];
                b[np * 2 + 1][0] = bb[2]; b[np * 2 + 1][1] = bb[3];
            }
#pragma unroll
            for (int mt = 0; mt < 4; ++mt)
#pragma unroll
                for (int nt = 0; nt < 4; ++nt)
                    MMA_BF16(acc[mt][nt], a[mt], b[nt]);
        }
    }
    __syncthreads();

    // epilogue: write sim, zero soft, accumulate per-row tile max
    float (*rowmax)[4] = (float(*)[4])smem;   // [128][4] (stage smem reused)
    const int g = lid >> 2, tig = lid & 3;
    const float2 z2 = make_float2(0.f, 0.f);
#pragma unroll
    for (int mt = 0; mt < 4; ++mt) {
        int mA = warp_m * 64 + mt * 16;
        float fi0 = invFsm[mA + g];
        float fi1 = invFsm[mA + g + 8];
        size_t row0 = (size_t)k * BB + m0 + mA + g;
        float* r0 = C + row0 * NN;
        float* r1 = r0 + 8 * NN;
        float* z0 = soft + row0 * NN;
        float* z1 = z0 + 8 * NN;
        float rm0 = -3.0e38f, rm1 = -3.0e38f;
#pragma unroll
        for (int nt = 0; nt < 4; ++nt) {
            int nA = warp_n * 32 + nt * 8 + tig * 2;
            int n = n0 + nA;
            float im0 = invMsm[nA], im1 = invMsm[nA + 1];
            float v00 = acc[mt][nt][0] * fi0 * im0;
            float v01 = acc[mt][nt][1] * fi0 * im1;
            float v10 = acc[mt][nt][2] * fi1 * im0;
            float v11 = acc[mt][nt][3] * fi1 * im1;
            if (n + 1 < NN) {
                *(float2*)(r0 + n) = make_float2(v00, v01);
                *(float2*)(r1 + n) = make_float2(v10, v11);
                *(float2*)(z0 + n) = z2;
                *(float2*)(z1 + n) = z2;
                rm0 = fmaxf(rm0, fmaxf(v00, v01));
                rm1 = fmaxf(rm1, fmaxf(v10, v11));
            } else if (n < NN) {
                r0[n] = v00; r1[n] = v10;
                z0[n] = 0.f; z1[n] = 0.f;
                rm0 = fmaxf(rm0, v00);
                rm1 = fmaxf(rm1, v10);
            }
        }
        // reduce across the 4 quad lanes (same g, different cols)
        rm0 = fmaxf(rm0, __shfl_xor_sync(0xFFFFFFFFu, rm0, 1));
        rm0 = fmaxf(rm0, __shfl_xor_sync(0xFFFFFFFFu, rm0, 2));
        rm1 = fmaxf(rm1, __shfl_xor_sync(0xFFFFFFFFu, rm1, 1));
        rm1 = fmaxf(rm1, __shfl_xor_sync(0xFFFFFFFFu, rm1, 2));
        if (tig == 0) {
            rowmax[mA + g][warp_n] = rm0;
            rowmax[mA + g + 8][warp_n] = rm1;
        }
    }
    __syncthreads();
    if (tid < 128) {
        float v = fmaxf(fmaxf(rowmax[tid][0], rowmax[tid][1]),
                        fmaxf(rowmax[tid][2], rowmax[tid][3]));
        bmax[((size_t)k * BB + m0 + tid) * NTILES + blockIdx.x] = v;
    }
}

// ---------------------------------------------------------------------------
// topk2: per row, (A) top-5 of 391 tile maxima -> threshold, (B) list tiles
// >= threshold, (C) exact top-5 over listed tiles only, softmax scatter.
// ---------------------------------------------------------------------------
__global__ void __launch_bounds__(256)
topk2_kernel(const float* __restrict__ bmax,
             const float* __restrict__ sim, float* __restrict__ soft) {
    const int row = blockIdx.x;
    const int tid = threadIdx.x;
    const float* bm = bmax + (size_t)row * NTILES;
    const float* s  = sim + (size_t)row * NN;

    __shared__ float sv[256 * TOPK];
    __shared__ int   si[256 * TOPK];
    __shared__ float rv[256];
    __shared__ int   ri[256];
    __shared__ float winV[TOPK];
    __shared__ int   winI[TOPK];
    __shared__ int   list[NTILES];
    __shared__ int   cnt;

    float tv[TOPK];
    int   ti[TOPK];

    auto insert = [&](float v, int idx) {
        if (v > tv[TOPK - 1]) {
            tv[TOPK - 1] = v; ti[TOPK - 1] = idx;
#pragma unroll
            for (int p = TOPK - 1; p > 0; --p) {
                if (tv[p] > tv[p - 1]) {
                    float t = tv[p]; tv[p] = tv[p - 1]; tv[p - 1] = t;
                    int   q = ti[p]; ti[p] = ti[p - 1]; ti[p - 1] = q;
                }
            }
        }
    };

    auto block_reduce_top5 = [&]() {
#pragma unroll
        for (int q = 0; q < TOPK; ++q) {
            sv[tid * TOPK + q] = tv[q];
            si[tid * TOPK + q] = ti[q];
        }
        __syncthreads();
        for (int r = 0; r < TOPK; ++r) {
            float m = -3.0e38f; int ms = -1;
#pragma unroll
            for (int j = 0; j < TOPK; ++j) {
                int slot = tid * TOPK + j;
                if (sv[slot] > m) { m = sv[slot]; ms = slot; }
            }
            rv[tid] = m; ri[tid] = ms;
            __syncthreads();
            for (int off = 128; off; off >>= 1) {
                if (tid < off && rv[tid + off] > rv[tid]) {
                    rv[tid] = rv[tid + off]; ri[tid] = ri[tid + off];
                }
                __syncthreads();
            }
            if (tid == 0) {
                int slot = ri[0];
                winV[r] = rv[0];
                winI[r] = si[slot];
                sv[slot] = -3.0e38f;
            }
            __syncthreads();
        }
    };

    // --- phase A: top-5 tile maxima -> threshold ---
#pragma unroll
    for (int q = 0; q < TOPK; ++q) { tv[q] = -3.0e38f; ti[q] = -1; }
    for (int i = tid; i < NTILES; i += 256) insert(bm[i], i);
    block_reduce_top5();
    const float thr = winV[TOPK - 1];

    // --- phase B: collect tiles with bmax >= thr ---
    if (tid == 0) cnt = 0;
    __syncthreads();
    for (int i = tid; i < NTILES; i += 256)
        if (bm[i] >= thr) list[atomicAdd(&cnt, 1)] = i;
    __syncthreads();
    const int nl = cnt;

    // --- phase C: exact top-5 over listed tiles ---
#pragma unroll
    for (int q = 0; q < TOPK; ++q) { tv[q] = -3.0e38f; ti[q] = -1; }
    const int total = nl * 128;
    for (int e = tid; e < total; e += 256) {
        int tile = list[e >> 7];
        int n = (tile << 7) + (e & 127);
        if (n < NN) insert(s[n], n);
    }
    block_reduce_top5();

    // --- softmax + scatter (soft rows pre-zeroed by GEMM) ---
    if (tid == 0) {
        float mx = winV[0];
        float w[TOPK], sum = 0.0f;
#pragma unroll
        for (int q = 0; q < TOPK; ++q) {
            w[q] = __expf((winV[q] - mx) * (1.0f / 3.0f));
            sum += w[q];
        }
        float invSum = 1.0f / sum;
        float* srow = soft + (size_t)row * NN;
#pragma unroll
        for (int q = 0; q < TOPK; ++q)
            srow[winI[q]] = w[q] * invSum;
    }
}

// ---------------------------------------------------------------------------
extern "C" void kernel_launch(void* const* d_in, const int* in_sizes, int n_in,
                              void* d_out, int out_size) {
    const float* feat = (const float*)d_in[0];  // [KP,BB,DD]
    const float* mem  = (const float*)d_in[1];  // [KP,NN,DD]
    float* out = (float*)d_out;

    const size_t total = (size_t)KP * BB * NN;

    float *invF, *invM, *bmax;
    __nv_bfloat16 *Asp, *Bsp;
    cudaGetSymbolAddress((void**)&invF, g_invF);
    cudaGetSymbolAddress((void**)&invM, g_invM);
    cudaGetSymbolAddress((void**)&Asp, g_Asplit);
    cudaGetSymbolAddress((void**)&Bsp, g_Bsplit);
    cudaGetSymbolAddress((void**)&bmax, g_bmax);

    float* soft = out;
    float* sim;
    if ((size_t)out_size >= 2 * total) {
        sim = out + total;
    } else {
        cudaGetSymbolAddress((void**)&sim, g_simScratch);
    }

    // fused norm + bf16 hi/lo split
    {
        int rowsF = KP * BB;
        norm_split_kernel<<<(rowsF + 7) / 8, 256>>>(feat, Asp, invF, rowsF);
        int rowsM = KP * NN;
        norm_split_kernel<<<(rowsM + 7) / 8, 256>>>(mem, Bsp, invM, rowsM);
    }

    // HMMA GEMM (+ zero-fill soft, + per-tile row maxima)
    {
        cudaFuncSetAttribute(gemm_hmma_kernel,
                             cudaFuncAttributeMaxDynamicSharedMemorySize, GEMM_SMEM);
        dim3 grid((NN + BN - 1) / BN, BB / BM, KP);  // (391, 2, 6)
        gemm_hmma_kernel<<<grid, 256, GEMM_SMEM>>>(Asp, Bsp, sim, soft,
                                                   invF, invM, bmax);
    }

    // hierarchical top-5 + softmax scatter
    topk2_kernel<<<KP * BB, 256>>>(bmax, sim, soft);
}

// round 12
// speedup vs baseline: 2.1196x; 1.4502x over previous
#include <cuda_runtime.h>
#include <cuda_fp16.h>
#include <cstdint>

#define KP 6
#define BB 256
#define DD 256
#define NN 50000
#define TOPK 5
#define NTILES 391                         // ceil(NN/128)
#define NCAND 16                           // approx candidates for exact rescore

// ---------------------------------------------------------------------------
// static device scratch
// ---------------------------------------------------------------------------
__device__ float g_invF[KP * BB];
__device__ float g_invM[KP * NN];
__device__ __half g_Asplit[(size_t)KP * BB * 512];   // [k][m][hi(256)|lo(256)] fp16
__device__ __half g_Bh[(size_t)KP * NN * 256];       // [k][n][256] fp16 (hi only)
__device__ float g_simScratch[(size_t)KP * BB * NN]; // fallback only
__device__ float g_bmax[(size_t)KP * BB * NTILES];   // per-row per-tile max

// ---------------------------------------------------------------------------
// helpers
// ---------------------------------------------------------------------------
__device__ __forceinline__ uint32_t smem_u32(const void* p) {
    uint32_t a;
    asm("{ .reg .u64 t; cvta.to.shared.u64 t, %1; cvt.u32.u64 %0, t; }"
        : "=r"(a) : "l"(p));
    return a;
}

#define CP16(dst, src) \
    asm volatile("cp.async.cg.shared.global [%0], [%1], 16;" \
                 :: "r"(dst), "l"(src) : "memory")
#define CP_COMMIT() asm volatile("cp.async.commit_group;" ::: "memory")
#define CP_WAIT1()  asm volatile("cp.async.wait_group 1;" ::: "memory")

#define LDSM4(r, addr)                                                          \
    asm volatile("ldmatrix.sync.aligned.m8n8.x4.shared.b16 {%0,%1,%2,%3}, [%4];"\
                 : "=r"((r)[0]), "=r"((r)[1]), "=r"((r)[2]), "=r"((r)[3])       \
                 : "r"(addr))

#define MMA_F16(d, a, b)                                                        \
    asm volatile("mma.sync.aligned.m16n8k16.row.col.f32.f16.f16.f32 "           \
                 "{%0,%1,%2,%3}, {%4,%5,%6,%7}, {%8,%9}, {%0,%1,%2,%3};"        \
                 : "+f"((d)[0]), "+f"((d)[1]), "+f"((d)[2]), "+f"((d)[3])       \
                 : "r"((a)[0]), "r"((a)[1]), "r"((a)[2]), "r"((a)[3]),          \
                   "r"((b)[0]), "r"((b)[1]))

// ---------------------------------------------------------------------------
// norm + fp16 hi/lo split for feat (A). One warp per row.
// ---------------------------------------------------------------------------
__device__ __forceinline__ void split_writeA(__half* drow, int col, float4 v) {
    float xs[4] = {v.x, v.y, v.z, v.w};
    uint32_t hp[2], lp[2];
#pragma unroll
    for (int q = 0; q < 2; ++q) {
        __half h0 = __float2half_rn(xs[2 * q + 0]);
        __half h1 = __float2half_rn(xs[2 * q + 1]);
        __half l0 = __float2half_rn(xs[2 * q + 0] - __half2float(h0));
        __half l1 = __float2half_rn(xs[2 * q + 1] - __half2float(h1));
        hp[q] = (uint32_t)__half_as_ushort(h0) | ((uint32_t)__half_as_ushort(h1) << 16);
        lp[q] = (uint32_t)__half_as_ushort(l0) | ((uint32_t)__half_as_ushort(l1) << 16);
    }
    *(uint2*)(drow + col)       = make_uint2(hp[0], hp[1]);
    *(uint2*)(drow + 256 + col) = make_uint2(lp[0], lp[1]);
}

__global__ void norm_splitA_kernel(const float* __restrict__ x,
                                   __half* __restrict__ dst,
                                   float* __restrict__ inv, int rows) {
    int warp = (blockIdx.x * blockDim.x + threadIdx.x) >> 5;
    int lane = threadIdx.x & 31;
    if (warp >= rows) return;
    const float4* p = (const float4*)(x + (size_t)warp * DD);
    float4 v0 = p[lane];
    float4 v1 = p[lane + 32];
    float s = v0.x * v0.x + v0.y * v0.y + v0.z * v0.z + v0.w * v0.w
            + v1.x * v1.x + v1.y * v1.y + v1.z * v1.z + v1.w * v1.w;
#pragma unroll
    for (int o = 16; o; o >>= 1) s += __shfl_xor_sync(0xFFFFFFFFu, s, o);
    if (lane == 0) inv[warp] = 1.0f / fmaxf(sqrtf(s), 1e-12f);

    __half* drow = dst + (size_t)warp * 512;
    split_writeA(drow, lane * 4, v0);
    split_writeA(drow, lane * 4 + 128, v1);
}

// ---------------------------------------------------------------------------
// norm + fp16 convert (hi only) for memory_bank (B). One warp per row.
// ---------------------------------------------------------------------------
__device__ __forceinline__ void writeB(__half* drow, int col, float4 v) {
    __half h0 = __float2half_rn(v.x), h1 = __float2half_rn(v.y);
    __half h2 = __float2half_rn(v.z), h3 = __float2half_rn(v.w);
    uint32_t p0 = (uint32_t)__half_as_ushort(h0) | ((uint32_t)__half_as_ushort(h1) << 16);
    uint32_t p1 = (uint32_t)__half_as_ushort(h2) | ((uint32_t)__half_as_ushort(h3) << 16);
    *(uint2*)(drow + col) = make_uint2(p0, p1);
}

__global__ void norm_convB_kernel(const float* __restrict__ x,
                                  __half* __restrict__ dst,
                                  float* __restrict__ inv, int rows) {
    int warp = (blockIdx.x * blockDim.x + threadIdx.x) >> 5;
    int lane = threadIdx.x & 31;
    if (warp >= rows) return;
    const float4* p = (const float4*)(x + (size_t)warp * DD);
    float4 v0 = p[lane];
    float4 v1 = p[lane + 32];
    float s = v0.x * v0.x + v0.y * v0.y + v0.z * v0.z + v0.w * v0.w
            + v1.x * v1.x + v1.y * v1.y + v1.z * v1.z + v1.w * v1.w;
#pragma unroll
    for (int o = 16; o; o >>= 1) s += __shfl_xor_sync(0xFFFFFFFFu, s, o);
    if (lane == 0) inv[warp] = 1.0f / fmaxf(sqrtf(s), 1e-12f);

    __half* drow = dst + (size_t)warp * 256;
    writeB(drow, lane * 4, v0);
    writeB(drow, lane * 4 + 128, v1);
}

// ---------------------------------------------------------------------------
// fp16 HMMA GEMM, 2-term A split sharing one B tile per chunk.
// 8 kc chunks of 32. 3-stage ring, depth-2 prefetch.
// + fused soft zero-fill + per-(row,tile) max into g_bmax.
// ---------------------------------------------------------------------------
#define BM 128
#define BN 128
#define NCHUNK 8
#define STAGES 3
#define TILE_BYTES (128 * 40 * 2)          // 10240 (80B rows)
#define STAGE_BYTES (3 * TILE_BYTES)       // Ahi + Alo + B
#define GEMM_SMEM (STAGES * STAGE_BYTES + 1024)

__global__ void __launch_bounds__(256)
gemm_hmma_kernel(const __half* __restrict__ Asp,
                 const __half* __restrict__ Bh,
                 float* __restrict__ C,
                 float* __restrict__ soft,
                 const float* __restrict__ invF,
                 const float* __restrict__ invM,
                 float* __restrict__ bmax) {
    extern __shared__ char smem[];
    const int k  = blockIdx.z;
    const int m0 = blockIdx.y * BM;
    const int n0 = blockIdx.x * BN;
    const int tid = threadIdx.x;
    const int wid = tid >> 5, lid = tid & 31;

    float* invFsm = (float*)(smem + STAGES * STAGE_BYTES);
    float* invMsm = invFsm + 128;
    if (tid < 128) {
        invFsm[tid] = invF[k * BB + m0 + tid];
    } else {
        int t = tid - 128;
        int n = n0 + t;
        invMsm[t] = (n < NN) ? invM[k * NN + n] : 0.0f;
    }

    const __half* Ak = Asp + (size_t)k * BB * 512;
    const __half* Bk = Bh + (size_t)k * NN * 256;
    const uint32_t sbase = smem_u32(smem);

    auto issue_chunk = [&](int c) {
        const uint32_t s = sbase + (c % STAGES) * STAGE_BYTES;
        const int ko = c * 32;
#pragma unroll
        for (int it = 0; it < 2; ++it) {
            int i = tid + it * 256;
            int row = i >> 2, seg = i & 3;
            uint32_t so = row * 80 + seg * 16;
            const __half* arow = Ak + (size_t)(m0 + row) * 512 + ko + seg * 8;
            CP16(s + so, arow);                            // A hi
            CP16(s + TILE_BYTES + so, arow + 256);         // A lo
            int gr = min(n0 + row, NN - 1);
            CP16(s + 2 * TILE_BYTES + so,
                 Bk + (size_t)gr * 256 + ko + seg * 8);    // B
        }
        CP_COMMIT();
    };

    float acc[4][4][4];
#pragma unroll
    for (int mt = 0; mt < 4; ++mt)
#pragma unroll
        for (int nt = 0; nt < 4; ++nt)
#pragma unroll
            for (int r = 0; r < 4; ++r) acc[mt][nt][r] = 0.0f;

    issue_chunk(0);
    issue_chunk(1);

    const int warp_m = wid >> 2;
    const int warp_n = wid & 3;

    for (int c = 0; c < NCHUNK; ++c) {
        CP_WAIT1();
        __syncthreads();
        if (c + 2 < NCHUNK) issue_chunk(c + 2);

        const uint32_t sAh = sbase + (c % STAGES) * STAGE_BYTES;
        const uint32_t sAl = sAh + TILE_BYTES;
        const uint32_t sB  = sAh + 2 * TILE_BYTES;
#pragma unroll
        for (int ks = 0; ks < 2; ++ks) {
            uint32_t b[4][2];
#pragma unroll
            for (int np = 0; np < 2; ++np) {
                uint32_t bb[4];
                int grp = lid >> 3, r = lid & 7;
                int row = warp_n * 32 + np * 16 + (grp >> 1) * 8 + r;
                int col = ks * 16 + (grp & 1) * 8;
                LDSM4(bb, sB + row * 80 + col * 2);
                b[np * 2 + 0][0] = bb[0]; b[np * 2 + 0][1] = bb[1];
                b[np * 2 + 1][0] = bb[2]; b[np * 2 + 1][1] = bb[3];
            }
            uint32_t a[4][4];
#pragma unroll
            for (int mt = 0; mt < 4; ++mt) {
                int row = warp_m * 64 + mt * 16 + (lid & 15);
                int col = ks * 16 + (lid >> 4) * 8;
                LDSM4(a[mt], sAh + row * 80 + col * 2);
            }
#pragma unroll
            for (int mt = 0; mt < 4; ++mt)
#pragma unroll
                for (int nt = 0; nt < 4; ++nt)
                    MMA_F16(acc[mt][nt], a[mt], b[nt]);
#pragma unroll
            for (int mt = 0; mt < 4; ++mt) {
                int row = warp_m * 64 + mt * 16 + (lid & 15);
                int col = ks * 16 + (lid >> 4) * 8;
                LDSM4(a[mt], sAl + row * 80 + col * 2);
            }
#pragma unroll
            for (int mt = 0; mt < 4; ++mt)
#pragma unroll
                for (int nt = 0; nt < 4; ++nt)
                    MMA_F16(acc[mt][nt], a[mt], b[nt]);
        }
    }
    __syncthreads();

    // epilogue: write sim, zero soft, accumulate per-row tile max
    float (*rowmax)[4] = (float(*)[4])smem;
    const int g = lid >> 2, tig = lid & 3;
    const float2 z2 = make_float2(0.f, 0.f);
#pragma unroll
    for (int mt = 0; mt < 4; ++mt) {
        int mA = warp_m * 64 + mt * 16;
        float fi0 = invFsm[mA + g];
        float fi1 = invFsm[mA + g + 8];
        size_t row0 = (size_t)k * BB + m0 + mA + g;
        float* r0 = C + row0 * NN;
        float* r1 = r0 + 8 * NN;
        float* z0 = soft + row0 * NN;
        float* z1 = z0 + 8 * NN;
        float rm0 = -3.0e38f, rm1 = -3.0e38f;
#pragma unroll
        for (int nt = 0; nt < 4; ++nt) {
            int nA = warp_n * 32 + nt * 8 + tig * 2;
            int n = n0 + nA;
            float im0 = invMsm[nA], im1 = invMsm[nA + 1];
            float v00 = acc[mt][nt][0] * fi0 * im0;
            float v01 = acc[mt][nt][1] * fi0 * im1;
            float v10 = acc[mt][nt][2] * fi1 * im0;
            float v11 = acc[mt][nt][3] * fi1 * im1;
            if (n + 1 < NN) {
                *(float2*)(r0 + n) = make_float2(v00, v01);
                *(float2*)(r1 + n) = make_float2(v10, v11);
                *(float2*)(z0 + n) = z2;
                *(float2*)(z1 + n) = z2;
                rm0 = fmaxf(rm0, fmaxf(v00, v01));
                rm1 = fmaxf(rm1, fmaxf(v10, v11));
            } else if (n < NN) {
                r0[n] = v00; r1[n] = v10;
                z0[n] = 0.f; z1[n] = 0.f;
                rm0 = fmaxf(rm0, v00);
                rm1 = fmaxf(rm1, v10);
            }
        }
        rm0 = fmaxf(rm0, __shfl_xor_sync(0xFFFFFFFFu, rm0, 1));
        rm0 = fmaxf(rm0, __shfl_xor_sync(0xFFFFFFFFu, rm0, 2));
        rm1 = fmaxf(rm1, __shfl_xor_sync(0xFFFFFFFFu, rm1, 1));
        rm1 = fmaxf(rm1, __shfl_xor_sync(0xFFFFFFFFu, rm1, 2));
        if (tig == 0) {
            rowmax[mA + g][warp_n] = rm0;
            rowmax[mA + g + 8][warp_n] = rm1;
        }
    }
    __syncthreads();
    if (tid < 128) {
        float v = fmaxf(fmaxf(rowmax[tid][0], rowmax[tid][1]),
                        fmaxf(rowmax[tid][2], rowmax[tid][3]));
        bmax[((size_t)k * BB + m0 + tid) * NTILES + blockIdx.x] = v;
    }
}

// ---------------------------------------------------------------------------
// topk2: (A) top-5 tile maxima -> thr (with slack), (B) candidate tiles,
// (C) approx top-16 over candidates, (D) EXACT fp32 rescore of the 16 from
// the original inputs -> exact top-5, softmax, scatter.
// ---------------------------------------------------------------------------
__global__ void __launch_bounds__(256)
topk2_kernel(const float* __restrict__ bmax,
             const float* __restrict__ sim, float* __restrict__ soft,
             const float* __restrict__ feat, const float* __restrict__ mem,
             const float* __restrict__ invF, const float* __restrict__ invM) {
    const int row = blockIdx.x;
    const int tid = threadIdx.x;
    const int wid = tid >> 5, lid = tid & 31;
    const float* bm = bmax + (size_t)row * NTILES;
    const float* s  = sim + (size_t)row * NN;

    __shared__ float sv[256 * TOPK];
    __shared__ int   si[256 * TOPK];
    __shared__ float rv[256];
    __shared__ int   ri[256];
    __shared__ float winV[TOPK];
    __shared__ int   winI[TOPK];
    __shared__ float candV[NCAND];
    __shared__ int   candI[NCAND];
    __shared__ float exV[NCAND];
    __shared__ int   exI[NCAND];
    __shared__ int   list[NTILES];
    __shared__ int   cnt;

    float tv[TOPK];
    int   ti[TOPK];

    auto insert = [&](float v, int idx) {
        if (v > tv[TOPK - 1]) {
            tv[TOPK - 1] = v; ti[TOPK - 1] = idx;
#pragma unroll
            for (int p = TOPK - 1; p > 0; --p) {
                if (tv[p] > tv[p - 1]) {
                    float t = tv[p]; tv[p] = tv[p - 1]; tv[p - 1] = t;
                    int   q = ti[p]; ti[p] = ti[p - 1]; ti[p - 1] = q;
                }
            }
        }
    };

    // --- phase A: top-5 tile maxima -> threshold ---
#pragma unroll
    for (int q = 0; q < TOPK; ++q) { tv[q] = -3.0e38f; ti[q] = -1; }
    for (int i = tid; i < NTILES; i += 256) insert(bm[i], i);
#pragma unroll
    for (int q = 0; q < TOPK; ++q) {
        sv[tid * TOPK + q] = tv[q];
        si[tid * TOPK + q] = ti[q];
    }
    __syncthreads();
    for (int r = 0; r < TOPK; ++r) {
        float m = -3.0e38f; int ms = -1;
#pragma unroll
        for (int j = 0; j < TOPK; ++j) {
            int slot = tid * TOPK + j;
            if (sv[slot] > m) { m = sv[slot]; ms = slot; }
        }
        rv[tid] = m; ri[tid] = ms;
        __syncthreads();
        for (int off = 128; off; off >>= 1) {
            if (tid < off && rv[tid + off] > rv[tid]) {
                rv[tid] = rv[tid + off]; ri[tid] = ri[tid + off];
            }
            __syncthreads();
        }
        if (tid == 0) {
            int slot = ri[0];
            winV[r] = rv[0];
            winI[r] = si[slot];
            sv[slot] = -3.0e38f;
        }
        __syncthreads();
    }
    // slack >> approx error (1.7e-5) so no candidate tile is missed
    const float thr = winV[TOPK - 1] - 1e-4f;

    // --- phase B: collect candidate tiles ---
    if (tid == 0) cnt = 0;
    __syncthreads();
    for (int i = tid; i < NTILES; i += 256)
        if (bm[i] >= thr) list[atomicAdd(&cnt, 1)] = i;
    __syncthreads();
    const int nl = cnt;

    // --- phase C: per-thread top-5 over candidate elements ---
#pragma unroll
    for (int q = 0; q < TOPK; ++q) { tv[q] = -3.0e38f; ti[q] = -1; }
    const int total = nl * 128;
    for (int e = tid; e < total; e += 256) {
        int tile = list[e >> 7];
        int n = (tile << 7) + (e & 127);
        if (n < NN) insert(s[n], n);
    }
#pragma unroll
    for (int q = 0; q < TOPK; ++q) {
        sv[tid * TOPK + q] = tv[q];
        si[tid * TOPK + q] = ti[q];
    }
    __syncthreads();

    // warp 0: iterative argmax x16 over the 1280 pooled entries
    if (wid == 0) {
        for (int pass = 0; pass < NCAND; ++pass) {
            float m = -3.0e38f; int ms = -1;
            for (int j = lid; j < 256 * TOPK; j += 32)
                if (sv[j] > m) { m = sv[j]; ms = j; }
#pragma unroll
            for (int o = 16; o; o >>= 1) {
                float om = __shfl_xor_sync(0xFFFFFFFFu, m, o);
                int   oc = __shfl_xor_sync(0xFFFFFFFFu, ms, o);
                if (om > m || (om == m && oc >= 0 && oc < ms)) { m = om; ms = oc; }
            }
            if (lid == 0) {
                candV[pass] = m;
                candI[pass] = (ms >= 0) ? si[ms] : -1;
                if (ms >= 0) sv[ms] = -3.0e38f;
            }
            __syncwarp();
        }
    }
    __syncthreads();

    // --- phase D: exact fp32 rescore of the 16 candidates ---
    {
        int c = wid + ((lid >= 0) ? 0 : 0);   // warp w handles c = w and w+8
        for (c = wid; c < NCAND; c += 8) {
            int n = candI[c];
            if (n >= 0) {
                int k = row >> 8;             // row = k*BB + b, BB=256
                const float4* fr = (const float4*)(feat + (size_t)row * DD);
                const float4* mr = (const float4*)(mem + ((size_t)(k * NN + n)) * DD);
                float ssum = 0.0f;
#pragma unroll
                for (int j = 0; j < 2; ++j) {
                    float4 a = fr[lid + j * 32];
                    float4 b = mr[lid + j * 32];
                    ssum += a.x * b.x + a.y * b.y + a.z * b.z + a.w * b.w;
                }
#pragma unroll
                for (int o = 16; o; o >>= 1)
                    ssum += __shfl_xor_sync(0xFFFFFFFFu, ssum, o);
                if (lid == 0) {
                    exV[c] = ssum * invF[row] * invM[k * NN + n];
                    exI[c] = n;
                }
            } else if (lid == 0) {
                exV[c] = -3.0e38f;
                exI[c] = -1;
            }
        }
    }
    __syncthreads();

    // --- exact top-5 among 16, softmax, scatter ---
    if (tid == 0) {
#pragma unroll
        for (int q = 0; q < TOPK; ++q) { tv[q] = -3.0e38f; ti[q] = -1; }
#pragma unroll
        for (int c = 0; c < NCAND; ++c) insert(exV[c], exI[c]);
        float mx = tv[0];
        float w[TOPK], sum = 0.0f;
#pragma unroll
        for (int q = 0; q < TOPK; ++q) {
            w[q] = __expf((tv[q] - mx) * (1.0f / 3.0f));
            sum += w[q];
        }
        float invSum = 1.0f / sum;
        float* srow = soft + (size_t)row * NN;
#pragma unroll
        for (int q = 0; q < TOPK; ++q)
            srow[ti[q]] = w[q] * invSum;
    }
}

// ---------------------------------------------------------------------------
extern "C" void kernel_launch(void* const* d_in, const int* in_sizes, int n_in,
                              void* d_out, int out_size) {
    const float* feat = (const float*)d_in[0];  // [KP,BB,DD]
    const float* mem  = (const float*)d_in[1];  // [KP,NN,DD]
    float* out = (float*)d_out;

    const size_t total = (size_t)KP * BB * NN;

    float *invF, *invM, *bmax;
    __half *Asp, *Bh;
    cudaGetSymbolAddress((void**)&invF, g_invF);
    cudaGetSymbolAddress((void**)&invM, g_invM);
    cudaGetSymbolAddress((void**)&Asp, g_Asplit);
    cudaGetSymbolAddress((void**)&Bh, g_Bh);
    cudaGetSymbolAddress((void**)&bmax, g_bmax);

    float* soft = out;
    float* sim;
    if ((size_t)out_size >= 2 * total) {
        sim = out + total;
    } else {
        cudaGetSymbolAddress((void**)&sim, g_simScratch);
    }

    // norms + fp16 conversions
    {
        int rowsF = KP * BB;
        norm_splitA_kernel<<<(rowsF + 7) / 8, 256>>>(feat, Asp, invF, rowsF);
        int rowsM = KP * NN;
        norm_convB_kernel<<<(rowsM + 7) / 8, 256>>>(mem, Bh, invM, rowsM);
    }

    // fp16 HMMA GEMM (+ zero-fill soft, + per-tile row maxima)
    {
        cudaFuncSetAttribute(gemm_hmma_kernel,
                             cudaFuncAttributeMaxDynamicSharedMemorySize, GEMM_SMEM);
        dim3 grid((NN + BN - 1) / BN, BB / BM, KP);  // (391, 2, 6)
        gemm_hmma_kernel<<<grid, 256, GEMM_SMEM>>>(Asp, Bh, sim, soft,
                                                   invF, invM, bmax);
    }

    // hierarchical top-5 with exact rescore + softmax scatter
    topk2_kernel<<<KP * BB, 256>>>(bmax, sim, soft, feat, mem, invF, invM);
}